// round 5
// baseline (speedup 1.0000x reference)
#include <cuda_runtime.h>
#include <cstdint>

#define N_NODES 100000
#define CAP 64          // per-node bucket capacity; P(Poisson(16) > 64) ~ 1e-20

// Scratch (device globals — no runtime allocation allowed).
__device__ int g_cursor[N_NODES];                  // doubles as in-degree
__device__ int g_slot[(size_t)N_NODES * CAP];      // edge ids, 25.6 MB (L2-resident)

// ---------------------------------------------------------------------------
// Kernel 1: bucket fill. One thread per edge (max chip-wide MLP): claim a
// slot in dst's bucket, store the edge id.
// ---------------------------------------------------------------------------
__global__ void __launch_bounds__(256)
fill_kernel(const int* __restrict__ dst, int n_edges)
{
    int e = blockIdx.x * blockDim.x + threadIdx.x;
    if (e >= n_edges) return;
    int d = __ldg(&dst[e]);
    int pos = atomicAdd(&g_cursor[d], 1);
    if (pos < CAP)
        g_slot[(size_t)d * CAP + pos] = e;
}

// ---------------------------------------------------------------------------
// Kernel 2: gather + reduce + finalize. 8 threads per node, one float4 lane
// each. Interleaved unroll-2 (R3-proven schedule). src recovered via
// L2-resident src[eid]; runs in parallel with the pat DRAM fetch.
// ---------------------------------------------------------------------------
__global__ void __launch_bounds__(256)
gather_kernel(const float4* __restrict__ rel,      // [N, 8] float4
              const float4* __restrict__ pat,      // [E, 8] float4
              const int*    __restrict__ src,      // [E] int32 (L2-resident)
              float4* __restrict__ out)            // [N, 8] float4
{
    int t = blockIdx.x * blockDim.x + threadIdx.x;
    int node = t >> 3;
    int lane = t & 7;
    if (node >= N_NODES) return;

    int deg = g_cursor[node];
    int n = min(deg, CAP);
    const int* slots = &g_slot[(size_t)node * CAP];

    float4 acc = make_float4(0.f, 0.f, 0.f, 0.f);

    int i = 0;
    for (; i + 2 <= n; i += 2) {
        int2 e2 = __ldg((const int2*)&slots[i]);   // 2 edge ids (8B aligned)

        int    s0 = __ldg(&src[e2.x]);
        float4 p0 = __ldcs(&pat[(size_t)e2.x * 8 + lane]);  // streaming: protect L2
        int    s1 = __ldg(&src[e2.y]);
        float4 p1 = __ldcs(&pat[(size_t)e2.y * 8 + lane]);
        float4 r0 = __ldg (&rel[(size_t)s0 * 8 + lane]);
        float4 r1 = __ldg (&rel[(size_t)s1 * 8 + lane]);

        acc.x = fmaf(r0.x, p0.x, acc.x);
        acc.y = fmaf(r0.y, p0.y, acc.y);
        acc.z = fmaf(r0.z, p0.z, acc.z);
        acc.w = fmaf(r0.w, p0.w, acc.w);
        acc.x = fmaf(r1.x, p1.x, acc.x);
        acc.y = fmaf(r1.y, p1.y, acc.y);
        acc.z = fmaf(r1.z, p1.z, acc.z);
        acc.w = fmaf(r1.w, p1.w, acc.w);
    }
    if (i < n) {
        int e0 = __ldg(&slots[i]);
        int s0 = __ldg(&src[e0]);
        float4 p0 = __ldcs(&pat[(size_t)e0 * 8 + lane]);
        float4 r0 = __ldg (&rel[(size_t)s0 * 8 + lane]);
        acc.x = fmaf(r0.x, p0.x, acc.x);
        acc.y = fmaf(r0.y, p0.y, acc.y);
        acc.z = fmaf(r0.z, p0.z, acc.z);
        acc.w = fmaf(r0.w, p0.w, acc.w);
    }

    float inv = 1.0f / fmaxf((float)deg, 1.0f);
    float4 rl = __ldg(&rel[node * 8 + lane]);
    float4 o;
    o.x = fmaf(acc.x, inv, rl.x);
    o.y = fmaf(acc.y, inv, rl.y);
    o.z = fmaf(acc.z, inv, rl.z);
    o.w = fmaf(acc.w, inv, rl.w);
    out[node * 8 + lane] = o;
}

// ---------------------------------------------------------------------------
extern "C" void kernel_launch(void* const* d_in, const int* in_sizes, int n_in,
                              void* d_out, int out_size)
{
    const float4* rel = (const float4*)d_in[0];     // [N, 32] f32
    const float4* pat = (const float4*)d_in[1];     // [E, 32] f32
    const int*    src = (const int*)d_in[2];        // [E] int32
    const int*    dst = (const int*)d_in[3];        // [E] int32
    float4* out = (float4*)d_out;

    const int n_edges = in_sizes[2];                // 1,600,000

    // 1) zero bucket cursors via async memset (graph-capturable, no SM launch)
    void* cursor_ptr = nullptr;
    cudaGetSymbolAddress(&cursor_ptr, g_cursor);
    cudaMemsetAsync(cursor_ptr, 0, N_NODES * sizeof(int));

    // 2) bucket fill: one thread per edge
    fill_kernel<<<(n_edges + 255) / 256, 256>>>(dst, n_edges);

    // 3) gather + mean + residual add
    int total_threads = N_NODES * 8;
    gather_kernel<<<(total_threads + 255) / 256, 256>>>(rel, pat, src, out);
}

// round 6
// speedup vs baseline: 1.2739x; 1.2739x over previous
#include <cuda_runtime.h>
#include <cstdint>

#define N_NODES 100000
#define CAP 64          // per-node bucket capacity; P(Poisson(16) > 64) ~ 1e-20

// Scratch (device globals — no runtime allocation allowed).
__device__ int  g_cursor[N_NODES];                  // doubles as in-degree
__device__ int2 g_slot[(size_t)N_NODES * CAP];      // (src, edge_id), 51.2 MB

// ---------------------------------------------------------------------------
// Kernel 1: bucket fill. One thread per edge (max chip-wide MLP).
// ---------------------------------------------------------------------------
__global__ void __launch_bounds__(256)
fill_kernel(const int* __restrict__ src, const int* __restrict__ dst, int n_edges)
{
    int e = blockIdx.x * blockDim.x + threadIdx.x;
    if (e >= n_edges) return;
    int s = __ldg(&src[e]);
    int d = __ldg(&dst[e]);
    int pos = atomicAdd(&g_cursor[d], 1);
    if (pos < CAP)
        g_slot[(size_t)d * CAP + pos] = make_int2(s, e);
}

// ---------------------------------------------------------------------------
// Kernel 2: gather. ONE WARP PER NODE.
//   lane = sub*8 + feat ; sub in [0,4) walks edges sub, sub+4, ... ;
//   feat in [0,8) owns one float4 of the 32-float feature row.
// 4 independent edge chains per warp -> deep MLP, zero intra-warp degree
// divergence. shfl_xor tree (8, 16) folds the 4 sub-accumulators.
// ---------------------------------------------------------------------------
__global__ void __launch_bounds__(256)
gather_kernel(const float4* __restrict__ rel,      // [N, 8] float4
              const float4* __restrict__ pat,      // [E, 8] float4
              float4* __restrict__ out)            // [N, 8] float4
{
    int node = (blockIdx.x * blockDim.x + threadIdx.x) >> 5;   // warp id
    if (node >= N_NODES) return;
    int lane = threadIdx.x & 31;
    int sub  = lane >> 3;          // 0..3
    int feat = lane & 7;           // 0..7

    int deg = g_cursor[node];
    int n = min(deg, CAP);
    const int2* slots = &g_slot[(size_t)node * CAP];

    float4 acc = make_float4(0.f, 0.f, 0.f, 0.f);

    // Each sub walks its strided slice; unroll-2 -> 2 edges in flight per sub,
    // 8 per warp.
    int i = sub;
    for (; i + 4 < n; i += 8) {
        int2 a = __ldg(&slots[i]);        // broadcast within the 8-lane group
        int2 b = __ldg(&slots[i + 4]);

        float4 p0 = __ldcs(&pat[(size_t)a.y * 8 + feat]);   // streaming
        float4 r0 = __ldg (&rel[(size_t)a.x * 8 + feat]);
        float4 p1 = __ldcs(&pat[(size_t)b.y * 8 + feat]);
        float4 r1 = __ldg (&rel[(size_t)b.x * 8 + feat]);

        acc.x = fmaf(r0.x, p0.x, acc.x);
        acc.y = fmaf(r0.y, p0.y, acc.y);
        acc.z = fmaf(r0.z, p0.z, acc.z);
        acc.w = fmaf(r0.w, p0.w, acc.w);
        acc.x = fmaf(r1.x, p1.x, acc.x);
        acc.y = fmaf(r1.y, p1.y, acc.y);
        acc.z = fmaf(r1.z, p1.z, acc.z);
        acc.w = fmaf(r1.w, p1.w, acc.w);
    }
    if (i < n) {
        int2 a = __ldg(&slots[i]);
        float4 p0 = __ldcs(&pat[(size_t)a.y * 8 + feat]);
        float4 r0 = __ldg (&rel[(size_t)a.x * 8 + feat]);
        acc.x = fmaf(r0.x, p0.x, acc.x);
        acc.y = fmaf(r0.y, p0.y, acc.y);
        acc.z = fmaf(r0.z, p0.z, acc.z);
        acc.w = fmaf(r0.w, p0.w, acc.w);
    }

    // Fold the 4 sub-accumulators: lanes 8 apart hold the same feat.
    acc.x += __shfl_xor_sync(0xFFFFFFFFu, acc.x, 8);
    acc.y += __shfl_xor_sync(0xFFFFFFFFu, acc.y, 8);
    acc.z += __shfl_xor_sync(0xFFFFFFFFu, acc.z, 8);
    acc.w += __shfl_xor_sync(0xFFFFFFFFu, acc.w, 8);
    acc.x += __shfl_xor_sync(0xFFFFFFFFu, acc.x, 16);
    acc.y += __shfl_xor_sync(0xFFFFFFFFu, acc.y, 16);
    acc.z += __shfl_xor_sync(0xFFFFFFFFu, acc.z, 16);
    acc.w += __shfl_xor_sync(0xFFFFFFFFu, acc.w, 16);

    if (sub == 0) {
        float inv = 1.0f / fmaxf((float)deg, 1.0f);
        float4 rl = __ldg(&rel[node * 8 + feat]);
        float4 o;
        o.x = fmaf(acc.x, inv, rl.x);
        o.y = fmaf(acc.y, inv, rl.y);
        o.z = fmaf(acc.z, inv, rl.z);
        o.w = fmaf(acc.w, inv, rl.w);
        out[node * 8 + feat] = o;
    }
}

// ---------------------------------------------------------------------------
extern "C" void kernel_launch(void* const* d_in, const int* in_sizes, int n_in,
                              void* d_out, int out_size)
{
    const float4* rel = (const float4*)d_in[0];     // [N, 32] f32
    const float4* pat = (const float4*)d_in[1];     // [E, 32] f32
    const int*    src = (const int*)d_in[2];        // [E] int32
    const int*    dst = (const int*)d_in[3];        // [E] int32
    float4* out = (float4*)d_out;

    const int n_edges = in_sizes[2];                // 1,600,000

    // 1) zero bucket cursors via async memset (graph-capturable, no SM launch)
    void* cursor_ptr = nullptr;
    cudaGetSymbolAddress(&cursor_ptr, g_cursor);
    cudaMemsetAsync(cursor_ptr, 0, N_NODES * sizeof(int));

    // 2) bucket fill: one thread per edge
    fill_kernel<<<(n_edges + 255) / 256, 256>>>(src, dst, n_edges);

    // 3) gather: one warp per node (8 warps per 256-thread block)
    gather_kernel<<<(N_NODES + 7) / 8, 256>>>(rel, pat, out);
}